// round 8
// baseline (speedup 1.0000x reference)
#include <cuda_runtime.h>
#include <math.h>

#define Bsz   2048
#define Fdim  128
#define Hdim  512
#define Tlen  96
#define G3H   1536
#define Mtile 16
#define NTHREADS 256

typedef unsigned long long ull;

// Transposed weights (k-major) in device scratch, ~4MB, L2-resident.
__device__ __align__(16) float d_WhhT[Hdim * G3H];  // [k][n] k<512, n<1536
__device__ __align__(16) float d_WihT[Fdim * G3H];  // [k][n] k<128, n<1536
__device__ __align__(16) float d_FcwT[Hdim * Fdim]; // [k][f] k<512, f<128

// ---- packed f32x2 helpers ----
__device__ __forceinline__ ull bcast2(float a) {
    ull r; unsigned int u = __float_as_uint(a);
    asm("mov.b64 %0, {%1, %1};" : "=l"(r) : "r"(u));
    return r;
}
__device__ __forceinline__ void fma2(ull& d, ull a, ull b) {
    asm("fma.rn.f32x2 %0, %1, %2, %0;" : "+l"(d) : "l"(a), "l"(b));
}
__device__ __forceinline__ float2 unpack2(ull v) {
    unsigned int lo, hi;
    asm("mov.b64 {%0, %1}, %2;" : "=r"(lo), "=r"(hi) : "l"(v));
    return make_float2(__uint_as_float(lo), __uint_as_float(hi));
}
__device__ __forceinline__ ull ld64(const float* p) {
    return *reinterpret_cast<const ull*>(p);
}

// One-time weight transpose
__global__ void gru_setup_kernel(const float* __restrict__ w_ih,
                                 const float* __restrict__ w_hh,
                                 const float* __restrict__ fc_w) {
    int idx = blockIdx.x * blockDim.x + threadIdx.x;
    if (idx < Hdim * G3H) {
        int k = idx / G3H, n = idx - k * G3H;
        d_WhhT[idx] = w_hh[n * Hdim + k];
    }
    int i2 = idx - Hdim * G3H;
    if (i2 >= 0 && i2 < Fdim * G3H) {
        int k = i2 / G3H, n = i2 - k * G3H;
        d_WihT[i2] = w_ih[n * Fdim + k];
    }
    int i3 = idx - Hdim * G3H - Fdim * G3H;
    if (i3 >= 0 && i3 < Hdim * Fdim) {
        int k = i3 / Fdim, f = i3 - k * Fdim;
        d_FcwT[i3] = fc_w[f * Hdim + k];
    }
}

// ---- register double-buffered 3-gate GEMM slab ----
// Per-thread tile: 8 m-rows x 2 n-cols (1 packed ull) x 3 gates.
// Weight buffers: 4 k-steps x 3 gates, A/B ping-pong.
template<int LD, int NIT>   // NIT = K/4, must be even
__device__ __forceinline__ void gemm3(
    const float* __restrict__ wbase,   // Wt + col (row k at wbase + k*G3H)
    const float* __restrict__ in,      // activations [m][LD] in smem
    int mrow0,
    ull (&aR)[8], ull (&aZ)[8], ull (&aX)[8])
{
    ull wA[4][3], wB[4][3];

    #pragma unroll
    for (int kk = 0; kk < 4; ++kk) {
        const float* w = wbase + (size_t)kk * G3H;
        wA[kk][0] = ld64(w); wA[kk][1] = ld64(w + 512); wA[kk][2] = ld64(w + 1024);
    }

    #pragma unroll 1
    for (int it = 0; it < NIT; it += 2) {
        // prefetch B <- stage it+1 (valid: NIT even)
        {
            const float* wr = wbase + (size_t)(it + 1) * 4 * G3H;
            #pragma unroll
            for (int kk = 0; kk < 4; ++kk) {
                const float* w = wr + (size_t)kk * G3H;
                wB[kk][0] = ld64(w); wB[kk][1] = ld64(w + 512); wB[kk][2] = ld64(w + 1024);
            }
        }
        // compute A @ stage it
        {
            const int k0 = it * 4;
            float4 av[8];
            #pragma unroll
            for (int i = 0; i < 8; ++i)
                av[i] = *reinterpret_cast<const float4*>(&in[(mrow0 + i) * LD + k0]);
            #pragma unroll
            for (int kk = 0; kk < 4; ++kk) {
                ull wr = wA[kk][0], wz = wA[kk][1], wn = wA[kk][2];
                #pragma unroll
                for (int i = 0; i < 8; ++i) {
                    ull a2 = bcast2(reinterpret_cast<const float*>(&av[i])[kk]);
                    fma2(aR[i], a2, wr);
                    fma2(aZ[i], a2, wz);
                    fma2(aX[i], a2, wn);
                }
            }
        }
        // prefetch A <- stage it+2 (clamped; clamped loads recompute same stage)
        {
            const int nx = (it + 2 < NIT) ? (it + 2) : it;
            const float* wr = wbase + (size_t)nx * 4 * G3H;
            #pragma unroll
            for (int kk = 0; kk < 4; ++kk) {
                const float* w = wr + (size_t)kk * G3H;
                wA[kk][0] = ld64(w); wA[kk][1] = ld64(w + 512); wA[kk][2] = ld64(w + 1024);
            }
        }
        // compute B @ stage it+1
        {
            const int k0 = (it + 1) * 4;
            float4 av[8];
            #pragma unroll
            for (int i = 0; i < 8; ++i)
                av[i] = *reinterpret_cast<const float4*>(&in[(mrow0 + i) * LD + k0]);
            #pragma unroll
            for (int kk = 0; kk < 4; ++kk) {
                ull wr = wB[kk][0], wz = wB[kk][1], wn = wB[kk][2];
                #pragma unroll
                for (int i = 0; i < 8; ++i) {
                    ull a2 = bcast2(reinterpret_cast<const float*>(&av[i])[kk]);
                    fma2(aR[i], a2, wr);
                    fma2(aZ[i], a2, wz);
                    fma2(aX[i], a2, wn);
                }
            }
        }
    }
}

__global__ __launch_bounds__(NTHREADS, 1)
void gru_kernel(const float* __restrict__ hidden,
                const float* __restrict__ b_ih,
                const float* __restrict__ b_hh,
                const float* __restrict__ fc_b,
                float* __restrict__ out) {
    extern __shared__ float smem[];
    float* hbufA = smem;                          // Mtile*Hdim
    float* hbufB = hbufA + Mtile * Hdim;          // Mtile*Hdim
    float* xbuf  = hbufB + Mtile * Hdim;          // Mtile*Fdim
    float* brz   = xbuf + Mtile * Fdim;           // 2*Hdim
    float* bin   = brz + 2 * Hdim;                // Hdim
    float* bhn   = bin + Hdim;                    // Hdim
    float* fcb   = bhn + Hdim;                    // Fdim

    const int tid = threadIdx.x;
    const int m0  = blockIdx.x * Mtile;

    for (int i = tid; i < Mtile * Hdim; i += NTHREADS) hbufA[i] = hidden[m0 * Hdim + i];
    for (int i = tid; i < Mtile * Fdim; i += NTHREADS) xbuf[i] = 0.f;
    for (int i = tid; i < 2 * Hdim; i += NTHREADS)     brz[i] = b_ih[i] + b_hh[i];
    for (int i = tid; i < Hdim; i += NTHREADS) {
        bin[i] = b_ih[2 * Hdim + i];
        bhn[i] = b_hh[2 * Hdim + i];
    }
    for (int i = tid; i < Fdim; i += NTHREADS)         fcb[i] = fc_b[i];
    __syncthreads();

    // Phase-1 mapping: 2 m-groups (8 rows) x 128 n-groups (2 cols);
    // 2 chunks of 256 n-cols per gate.
    const int mg    = tid >> 7;            // 0..1
    const int ng2   = (tid & 127) * 2;     // packed col pair within 256-chunk
    const int mrow0 = mg * 8;
    // Phase-2 mapping: 4 m-groups (4 rows) x 64 f-groups (2 cols)
    const int mh = tid >> 6;               // 0..3
    const int f0 = (tid & 63) * 2;

    float* hc = hbufA;
    float* hn = hbufB;

    for (int s = 0; s < Tlen; ++s) {
        // ===== Phase 1: gates + h update, 2 chunks of 256 n-cols per gate =====
        #pragma unroll 1
        for (int nc = 0; nc < 2; ++nc) {
            const int col = nc * 256 + ng2;

            ull aR[8], aZ[8], aN[8], aI[8];
            #pragma unroll
            for (int i = 0; i < 8; ++i) { aR[i] = 0; aZ[i] = 0; aN[i] = 0; aI[i] = 0; }

            // x contribution (K=128) -> aR, aZ, aI
            gemm3<Fdim, 32>(d_WihT + col, xbuf, mrow0, aR, aZ, aI);
            // h contribution (K=512) -> aR, aZ, aN
            gemm3<Hdim, 128>(d_WhhT + col, hc, mrow0, aR, aZ, aN);

            // epilogue: nonlinearity + h update on this thread's 8m x 2n patch
            const float2 br = *reinterpret_cast<const float2*>(&brz[col]);
            const float2 bz = *reinterpret_cast<const float2*>(&brz[Hdim + col]);
            const float2 bi = *reinterpret_cast<const float2*>(&bin[col]);
            const float2 bh = *reinterpret_cast<const float2*>(&bhn[col]);
            #pragma unroll
            for (int i = 0; i < 8; ++i) {
                const int m = mrow0 + i;
                float2 R = unpack2(aR[i]), Z = unpack2(aZ[i]);
                float2 N = unpack2(aN[i]), I = unpack2(aI[i]);
                float2 hp = *reinterpret_cast<const float2*>(&hc[m * Hdim + col]);

                float r0 = 1.f / (1.f + __expf(-(R.x + br.x)));
                float r1 = 1.f / (1.f + __expf(-(R.y + br.y)));
                float z0 = 1.f / (1.f + __expf(-(Z.x + bz.x)));
                float z1 = 1.f / (1.f + __expf(-(Z.y + bz.y)));
                float n0 = tanhf(I.x + bi.x + r0 * (N.x + bh.x));
                float n1 = tanhf(I.y + bi.y + r1 * (N.y + bh.y));
                float2 hv = make_float2((1.f - z0) * n0 + z0 * hp.x,
                                        (1.f - z1) * n1 + z1 * hp.y);
                *reinterpret_cast<float2*>(&hn[m * Hdim + col]) = hv;
            }
        }
        __syncthreads();   // hn complete

        // ===== Phase 2: x_new = h_new @ fc_w^T + fc_b (A/B pipelined, 4m x 2f) =====
        {
            ull acc[4] = {0ull, 0ull, 0ull, 0ull};
            ull fA[8], fB[8];
            const float* fw = d_FcwT + f0;

            #pragma unroll
            for (int kk = 0; kk < 8; ++kk)
                fA[kk] = ld64(fw + (size_t)kk * Fdim);

            #pragma unroll 1
            for (int it = 0; it < 64; it += 2) {
                #pragma unroll
                for (int kk = 0; kk < 8; ++kk)
                    fB[kk] = ld64(fw + (size_t)((it + 1) * 8 + kk) * Fdim);
                {
                    const int k0 = it * 8;
                    float4 av[4][2];
                    #pragma unroll
                    for (int i = 0; i < 4; ++i) {
                        const float* row = hn + (size_t)(mh * 4 + i) * Hdim + k0;
                        av[i][0] = *reinterpret_cast<const float4*>(row);
                        av[i][1] = *reinterpret_cast<const float4*>(row + 4);
                    }
                    #pragma unroll
                    for (int kk = 0; kk < 8; ++kk) {
                        #pragma unroll
                        for (int i = 0; i < 4; ++i) {
                            ull a2 = bcast2(
                                reinterpret_cast<const float*>(&av[i][kk >> 2])[kk & 3]);
                            fma2(acc[i], a2, fA[kk]);
                        }
                    }
                }
                {
                    const int nx = (it + 2 < 64) ? (it + 2) : it;
                    #pragma unroll
                    for (int kk = 0; kk < 8; ++kk)
                        fA[kk] = ld64(fw + (size_t)(nx * 8 + kk) * Fdim);
                }
                {
                    const int k0 = (it + 1) * 8;
                    float4 av[4][2];
                    #pragma unroll
                    for (int i = 0; i < 4; ++i) {
                        const float* row = hn + (size_t)(mh * 4 + i) * Hdim + k0;
                        av[i][0] = *reinterpret_cast<const float4*>(row);
                        av[i][1] = *reinterpret_cast<const float4*>(row + 4);
                    }
                    #pragma unroll
                    for (int kk = 0; kk < 8; ++kk) {
                        #pragma unroll
                        for (int i = 0; i < 4; ++i) {
                            ull a2 = bcast2(
                                reinterpret_cast<const float*>(&av[i][kk >> 2])[kk & 3]);
                            fma2(acc[i], a2, fB[kk]);
                        }
                    }
                }
            }

            const int trow = Tlen - 1 - s;   // reference reverses time at the end
            const float2 fb2 = *reinterpret_cast<const float2*>(&fcb[f0]);
            #pragma unroll
            for (int i = 0; i < 4; ++i) {
                const int m = mh * 4 + i;
                float2 v = unpack2(acc[i]);
                const float v0 = v.x + fb2.x;
                const float v1 = v.y + fb2.y;
                *reinterpret_cast<float2*>(&xbuf[m * Fdim + f0]) = make_float2(v0, v1);
                *reinterpret_cast<float2*>(
                    &out[((size_t)(m0 + m) * Tlen + trow) * Fdim + f0]) =
                    make_float2(v0, v1);
            }
        }
        __syncthreads();   // xbuf complete before next step's phase 1

        float* tmp = hc; hc = hn; hn = tmp;
    }
}

extern "C" void kernel_launch(void* const* d_in, const int* in_sizes, int n_in,
                              void* d_out, int out_size) {
    const float* hidden = (const float*)d_in[0];
    const float* w_ih   = (const float*)d_in[1];
    const float* w_hh   = (const float*)d_in[2];
    const float* b_ih   = (const float*)d_in[3];
    const float* b_hh   = (const float*)d_in[4];
    const float* fc_w   = (const float*)d_in[5];
    const float* fc_b   = (const float*)d_in[6];
    float* out = (float*)d_out;

    const int total = Hdim * G3H + Fdim * G3H + Hdim * Fdim;
    gru_setup_kernel<<<(total + 255) / 256, 256>>>(w_ih, w_hh, fc_w);

    const int smem_bytes =
        (2 * Mtile * Hdim + Mtile * Fdim + 2 * Hdim + Hdim + Hdim + Fdim) * (int)sizeof(float);
    cudaFuncSetAttribute(gru_kernel, cudaFuncAttributeMaxDynamicSharedMemorySize, smem_bytes);
    gru_kernel<<<Bsz / Mtile, NTHREADS, smem_bytes>>>(hidden, b_ih, b_hh, fc_b, out);
}